// round 1
// baseline (speedup 1.0000x reference)
#include <cuda_runtime.h>

#define B_SZ   8
#define T_SEQ  1024
#define C_DIM  768
#define C3     2304
#define NH     12
#define HS     64
#define SCALE_F 0.125f   /* 1/sqrt(64) */

// 8192 x 2304 fp32 scratch for fused QKV output (q|k|v concatenated per row)
__device__ float g_qkv[(size_t)B_SZ * T_SEQ * C3];

// ---------------------------------------------------------------------------
// Kernel 1: QKV projection  qkv[r,c] = x[r,:] @ W[:,c] + bias[c]
// 128x128 block tile, BK=16, 256 threads, 8x8 per thread.
// ---------------------------------------------------------------------------
__global__ __launch_bounds__(256) void qkv_gemm_kernel(
    const float* __restrict__ x,
    const float* __restrict__ W,
    const float* __restrict__ bias)
{
    __shared__ float As[16][128];   // A stored transposed: As[k][m]
    __shared__ float Bs[16][128];   // Bs[k][n]

    const int K = C_DIM, N = C3;
    const int tid = threadIdx.x;
    const int bm  = blockIdx.y * 128;
    const int bn  = blockIdx.x * 128;
    const int tx  = tid & 15;
    const int ty  = tid >> 4;

    float acc[8][8];
#pragma unroll
    for (int i = 0; i < 8; i++)
#pragma unroll
        for (int j = 0; j < 8; j++) acc[i][j] = 0.f;

    for (int k0 = 0; k0 < K; k0 += 16) {
        // Load A tile (128 rows x 16 cols), store transposed
#pragma unroll
        for (int l = 0; l < 2; l++) {
            int idx = tid + l * 256;          // 0..511 float4 slots
            int ar  = idx >> 2;               // 0..127
            int ac  = (idx & 3) << 2;         // 0,4,8,12
            float4 v = *(const float4*)(x + (size_t)(bm + ar) * K + k0 + ac);
            As[ac + 0][ar] = v.x;
            As[ac + 1][ar] = v.y;
            As[ac + 2][ar] = v.z;
            As[ac + 3][ar] = v.w;
        }
        // Load B tile (16 rows x 128 cols), direct float4
#pragma unroll
        for (int l = 0; l < 2; l++) {
            int idx = tid + l * 256;
            int br  = idx >> 5;               // 0..15
            int bc  = (idx & 31) << 2;        // 0..124
            *(float4*)(&Bs[br][bc]) =
                *(const float4*)(W + (size_t)(k0 + br) * N + bn + bc);
        }
        __syncthreads();

#pragma unroll
        for (int kk = 0; kk < 16; kk++) {
            float4 a0 = *(float4*)(&As[kk][ty * 8]);
            float4 a1 = *(float4*)(&As[kk][ty * 8 + 4]);
            float4 b0 = *(float4*)(&Bs[kk][tx * 8]);
            float4 b1 = *(float4*)(&Bs[kk][tx * 8 + 4]);
            float a[8] = {a0.x, a0.y, a0.z, a0.w, a1.x, a1.y, a1.z, a1.w};
            float b[8] = {b0.x, b0.y, b0.z, b0.w, b1.x, b1.y, b1.z, b1.w};
#pragma unroll
            for (int i = 0; i < 8; i++)
#pragma unroll
                for (int j = 0; j < 8; j++)
                    acc[i][j] = fmaf(a[i], b[j], acc[i][j]);
        }
        __syncthreads();
    }

    // Epilogue: add bias, vectorized store into qkv scratch
#pragma unroll
    for (int i = 0; i < 8; i++) {
        int r = bm + ty * 8 + i;
#pragma unroll
        for (int j4 = 0; j4 < 2; j4++) {
            int c = bn + tx * 8 + j4 * 4;
            float4 v;
            v.x = acc[i][j4 * 4 + 0] + bias[c + 0];
            v.y = acc[i][j4 * 4 + 1] + bias[c + 1];
            v.z = acc[i][j4 * 4 + 2] + bias[c + 2];
            v.w = acc[i][j4 * 4 + 3] + bias[c + 3];
            *(float4*)(g_qkv + (size_t)r * N + c) = v;
        }
    }
}

// ---------------------------------------------------------------------------
// Kernel 2: causal relu-attention, streaming over k-tiles.
// One block = one (b,h) pair x one 64-row q-tile. 256 threads, 4x4/thread.
// Smem: Qt (Q transposed [d][row]), KSt (K transposed, then scores transposed),
//       Vs (V direct [row][d]). Stride 68 breaks bank conflicts on LDS.128.
// ---------------------------------------------------------------------------
#define ST 68
#define ATTN_SMEM (3 * 64 * ST * 4)

__global__ __launch_bounds__(256) void attn_kernel(float* __restrict__ out)
{
    extern __shared__ float sm[];
    float* Qt  = sm;                 // [64 d][ST]
    float* KSt = sm + 64 * ST;       // Kt[d][row]  -> later  St[col][row]
    float* Vs  = sm + 2 * 64 * ST;   // [64 row][ST]

    const int tid = threadIdx.x;
    const int qb  = blockIdx.x;          // q tile index (0..15)
    const int bh  = blockIdx.y;          // 0..95
    const int b   = bh / NH;
    const int h   = bh % NH;
    const int tx  = tid & 15;
    const int ty  = tid >> 4;

    const float* base = g_qkv + (size_t)b * T_SEQ * C3 + h * HS;

    // Load Q tile transposed: Qt[d][row]
#pragma unroll
    for (int l = 0; l < 4; l++) {
        int idx = tid + l * 256;         // 0..1023 float4 slots
        int r   = idx >> 4;              // 0..63
        int c   = (idx & 15) << 2;       // 0..60
        float4 v = *(const float4*)(base + (size_t)(qb * 64 + r) * C3 + c);
        Qt[(c + 0) * ST + r] = v.x;
        Qt[(c + 1) * ST + r] = v.y;
        Qt[(c + 2) * ST + r] = v.z;
        Qt[(c + 3) * ST + r] = v.w;
    }

    float y[4][4];
#pragma unroll
    for (int i = 0; i < 4; i++)
#pragma unroll
        for (int j = 0; j < 4; j++) y[i][j] = 0.f;

    for (int kb = 0; kb <= qb; kb++) {
        __syncthreads();   // previous tile fully consumed (also orders Qt stores)

        // Load K (transposed) and V (direct) tiles for this k block
#pragma unroll
        for (int l = 0; l < 4; l++) {
            int idx = tid + l * 256;
            int r   = idx >> 4;
            int c   = (idx & 15) << 2;
            const float* kp = base + (size_t)(kb * 64 + r) * C3 + C_DIM + c;
            float4 kv = *(const float4*)kp;
            KSt[(c + 0) * ST + r] = kv.x;
            KSt[(c + 1) * ST + r] = kv.y;
            KSt[(c + 2) * ST + r] = kv.z;
            KSt[(c + 3) * ST + r] = kv.w;
            float4 vv = *(const float4*)(kp + C_DIM);
            *(float4*)(&Vs[r * ST + c]) = vv;
        }
        __syncthreads();

        // S = Q . K^T  (4x4 per thread, conflict-free LDS.128 outer product)
        float s[4][4];
#pragma unroll
        for (int i = 0; i < 4; i++)
#pragma unroll
            for (int j = 0; j < 4; j++) s[i][j] = 0.f;

#pragma unroll 8
        for (int d = 0; d < 64; d++) {
            float4 qa = *(float4*)(&Qt[d * ST + ty * 4]);
            float4 ka = *(float4*)(&KSt[d * ST + tx * 4]);
            float a[4] = {qa.x, qa.y, qa.z, qa.w};
            float bb[4] = {ka.x, ka.y, ka.z, ka.w};
#pragma unroll
            for (int i = 0; i < 4; i++)
#pragma unroll
                for (int j = 0; j < 4; j++)
                    s[i][j] = fmaf(a[i], bb[j], s[i][j]);
        }
        __syncthreads();   // done reading KSt as K

        // scale + relu + causal mask, store scores transposed: St[col][row]
#pragma unroll
        for (int j = 0; j < 4; j++) {
            int tk = kb * 64 + tx * 4 + j;
            float tmp[4];
#pragma unroll
            for (int i = 0; i < 4; i++) {
                int tq = qb * 64 + ty * 4 + i;
                float val = fmaxf(s[i][j] * SCALE_F, 0.f);
                if (tk > tq) val = 0.f;
                tmp[i] = val;
            }
            float4 sv = make_float4(tmp[0], tmp[1], tmp[2], tmp[3]);
            *(float4*)(&KSt[(tx * 4 + j) * ST + ty * 4]) = sv;
        }
        __syncthreads();

        // Y += S . V
#pragma unroll 8
        for (int c = 0; c < 64; c++) {
            float4 sa = *(float4*)(&KSt[c * ST + ty * 4]);
            float4 va = *(float4*)(&Vs[c * ST + tx * 4]);
            float a[4] = {sa.x, sa.y, sa.z, sa.w};
            float bb[4] = {va.x, va.y, va.z, va.w};
#pragma unroll
            for (int i = 0; i < 4; i++)
#pragma unroll
                for (int j = 0; j < 4; j++)
                    y[i][j] = fmaf(a[i], bb[j], y[i][j]);
        }
    }

    // Write out: out[b, t, h*64 + d]
#pragma unroll
    for (int i = 0; i < 4; i++) {
        int t = qb * 64 + ty * 4 + i;
        float4 v = make_float4(y[i][0], y[i][1], y[i][2], y[i][3]);
        *(float4*)(out + ((size_t)b * T_SEQ + t) * C_DIM + h * HS + tx * 4) = v;
    }
}

// ---------------------------------------------------------------------------
extern "C" void kernel_launch(void* const* d_in, const int* in_sizes, int n_in,
                              void* d_out, int out_size)
{
    const float* x    = (const float*)d_in[0];
    const float* W    = (const float*)d_in[1];
    const float* bias = (const float*)d_in[2];
    float* out        = (float*)d_out;

    // QKV projection: M=8192, N=2304, K=768
    qkv_gemm_kernel<<<dim3(C3 / 128, (B_SZ * T_SEQ) / 128), 256>>>(x, W, bias);

    // Attention: 16 q-tiles x 96 (b,h) pairs
    cudaFuncSetAttribute(attn_kernel,
                         cudaFuncAttributeMaxDynamicSharedMemorySize, ATTN_SMEM);
    attn_kernel<<<dim3(16, B_SZ * NH), 256, ATTN_SMEM>>>(out);
}

// round 3
// speedup vs baseline: 1.4827x; 1.4827x over previous
#include <cuda_runtime.h>
#include <cuda_bf16.h>
#include <cstdint>

#define B_SZ   8
#define T_SEQ  1024
#define C_DIM  768
#define C3     2304
#define NH     12
#define HS     64
#define SCALE_F 0.125f
#define M_ROWS (B_SZ * T_SEQ)       /* 8192 */

// fp32 scratch for fused QKV output (q|k|v per row)
__device__ float g_qkv[(size_t)M_ROWS * C3];
// bf16 hi/lo splits of x [8192,768] and W^T [2304,768] (K-contiguous)
__device__ __align__(16) __nv_bfloat16 g_xhi[(size_t)M_ROWS * C_DIM];
__device__ __align__(16) __nv_bfloat16 g_xlo[(size_t)M_ROWS * C_DIM];
__device__ __align__(16) __nv_bfloat16 g_wthi[(size_t)C3 * C_DIM];
__device__ __align__(16) __nv_bfloat16 g_wtlo[(size_t)C3 * C_DIM];

// ---------------------------------------------------------------------------
// helpers
// ---------------------------------------------------------------------------
__device__ __forceinline__ uint32_t smem_u32(const void* p) {
    uint32_t a;
    asm("{ .reg .u64 t; cvta.to.shared.u64 t, %1; cvt.u32.u64 %0, t; }"
        : "=r"(a) : "l"(p));
    return a;
}
#define SWZ128(off) ((off) ^ (((off) >> 3) & 0x70))

__device__ __forceinline__ void cp_async16(uint32_t saddr, const void* gaddr) {
    asm volatile("cp.async.cg.shared.global [%0], [%1], 16;"
                 :: "r"(saddr), "l"(gaddr) : "memory");
}
__device__ __forceinline__ void cp_commit() {
    asm volatile("cp.async.commit_group;" ::: "memory");
}
template <int N>
__device__ __forceinline__ void cp_wait() {
    asm volatile("cp.async.wait_group %0;" :: "n"(N) : "memory");
}
__device__ __forceinline__ void ldm_x4(uint32_t* r, uint32_t addr) {
    asm volatile("ldmatrix.sync.aligned.m8n8.x4.shared.b16 {%0,%1,%2,%3}, [%4];"
                 : "=r"(r[0]), "=r"(r[1]), "=r"(r[2]), "=r"(r[3]) : "r"(addr));
}
__device__ __forceinline__ void mma_bf16(float* c, const uint32_t* a,
                                         const uint32_t b0, const uint32_t b1) {
    asm volatile(
        "mma.sync.aligned.m16n8k16.row.col.f32.bf16.bf16.f32 "
        "{%0,%1,%2,%3}, {%4,%5,%6,%7}, {%8,%9}, {%0,%1,%2,%3};"
        : "+f"(c[0]), "+f"(c[1]), "+f"(c[2]), "+f"(c[3])
        : "r"(a[0]), "r"(a[1]), "r"(a[2]), "r"(a[3]), "r"(b0), "r"(b1));
}

// ---------------------------------------------------------------------------
// Prep kernels: bf16 hi/lo split of x; transpose+split of W
// ---------------------------------------------------------------------------
__global__ void prep_x_kernel(const float* __restrict__ x) {
    int i = blockIdx.x * blockDim.x + threadIdx.x;
    if (i >= M_ROWS * C_DIM) return;
    float v = x[i];
    __nv_bfloat16 hi = __float2bfloat16(v);
    g_xhi[i] = hi;
    g_xlo[i] = __float2bfloat16(v - __bfloat162float(hi));
}

__global__ void prep_w_kernel(const float* __restrict__ W) {
    __shared__ float t[32][33];
    int n0 = blockIdx.x * 32, k0 = blockIdx.y * 32;
    int tx = threadIdx.x, ty = threadIdx.y;
#pragma unroll
    for (int j = 0; j < 4; j++)
        t[ty + 8 * j][tx] = W[(size_t)(k0 + ty + 8 * j) * C3 + n0 + tx];
    __syncthreads();
#pragma unroll
    for (int j = 0; j < 4; j++) {
        float v = t[tx][ty + 8 * j];
        __nv_bfloat16 hi = __float2bfloat16(v);
        size_t o = (size_t)(n0 + ty + 8 * j) * C_DIM + k0 + tx;
        g_wthi[o] = hi;
        g_wtlo[o] = __float2bfloat16(v - __bfloat162float(hi));
    }
}

// ---------------------------------------------------------------------------
// Kernel 1: QKV projection via mma.sync bf16 3-term split.
// Block tile 128x128, K-chunk 64, 8 warps (warp tile 32x64), double-buffered.
// ---------------------------------------------------------------------------
#define BK       64
#define NCHUNK   (C_DIM / BK)          /* 12 */
#define TILE_B   (128 * 128)           /* 128 rows x 128 bytes = 16 KB */
#define STAGE_B  (4 * TILE_B)          /* A_hi, A_lo, B_hi, B_lo */
#define GEMM_SMEM (2 * STAGE_B)        /* 128 KB */

__device__ __forceinline__ void load_stage(uint32_t sbase, int bm, int bn,
                                           int k0, int tid)
{
#pragma unroll
    for (int i = 0; i < 4; i++) {
        int lin = i * 256 + tid;          // 0..1023
        int r   = lin >> 3;               // row 0..127
        int cb  = (lin & 7) * 16;         // byte col 0..112
        uint32_t sw = SWZ128((uint32_t)(r * 128 + cb));
        const char* ax = (const char*)(g_xhi + (size_t)(bm + r) * C_DIM + k0) + cb;
        cp_async16(sbase + 0 * TILE_B + sw, ax);
        const char* al = (const char*)(g_xlo + (size_t)(bm + r) * C_DIM + k0) + cb;
        cp_async16(sbase + 1 * TILE_B + sw, al);
        const char* bh = (const char*)(g_wthi + (size_t)(bn + r) * C_DIM + k0) + cb;
        cp_async16(sbase + 2 * TILE_B + sw, bh);
        const char* bl = (const char*)(g_wtlo + (size_t)(bn + r) * C_DIM + k0) + cb;
        cp_async16(sbase + 3 * TILE_B + sw, bl);
    }
    cp_commit();
}

__global__ __launch_bounds__(256, 1) void qkv_mma_kernel(const float* __restrict__ bias)
{
    extern __shared__ char sm[];
    const uint32_t sbase = smem_u32(sm);

    const int tid  = threadIdx.x;
    const int wid  = tid >> 5;
    const int lane = tid & 31;
    const int bn   = blockIdx.x * 128;
    const int bm   = blockIdx.y * 128;
    const int warp_m = (wid & 3) * 32;    // 0,32,64,96
    const int warp_n = (wid >> 2) * 64;   // 0,64

    // ldmatrix lane addressing: row = base + (lane&15), chunk = (lane>>4)*16B
    const int ldrow   = lane & 15;
    const int ldchunk = (lane >> 4) * 16;

    float acc[2][8][4];
#pragma unroll
    for (int mt = 0; mt < 2; mt++)
#pragma unroll
        for (int nt = 0; nt < 8; nt++)
#pragma unroll
            for (int q = 0; q < 4; q++) acc[mt][nt][q] = 0.f;

    // prologue
    load_stage(sbase, bm, bn, 0, tid);

    for (int ch = 0; ch < NCHUNK; ch++) {
        const uint32_t sstage = sbase + (uint32_t)(ch & 1) * STAGE_B;
        if (ch + 1 < NCHUNK) {
            load_stage(sbase + (uint32_t)((ch + 1) & 1) * STAGE_B,
                       bm, bn, (ch + 1) * BK, tid);
            cp_wait<1>();
        } else {
            cp_wait<0>();
        }
        __syncthreads();

#pragma unroll
        for (int ks = 0; ks < 4; ks++) {
            const int kb = ks * 32 + ldchunk;   // byte offset within 128B row

            uint32_t ah[2][4], al[2][4];
#pragma unroll
            for (int mt = 0; mt < 2; mt++) {
                uint32_t off = SWZ128((uint32_t)((warp_m + mt * 16 + ldrow) * 128 + kb));
                ldm_x4(ah[mt], sstage + 0 * TILE_B + off);
                ldm_x4(al[mt], sstage + 1 * TILE_B + off);
            }
            uint32_t bhv[8][2], blv[8][2];
#pragma unroll
            for (int np = 0; np < 4; np++) {
                uint32_t off = SWZ128((uint32_t)((warp_n + np * 16 + ldrow) * 128 + kb));
                uint32_t r[4];
                ldm_x4(r, sstage + 2 * TILE_B + off);
                bhv[2 * np][0] = r[0]; bhv[2 * np][1] = r[2];
                bhv[2 * np + 1][0] = r[1]; bhv[2 * np + 1][1] = r[3];
                ldm_x4(r, sstage + 3 * TILE_B + off);
                blv[2 * np][0] = r[0]; blv[2 * np][1] = r[2];
                blv[2 * np + 1][0] = r[1]; blv[2 * np + 1][1] = r[3];
            }
#pragma unroll
            for (int mt = 0; mt < 2; mt++)
#pragma unroll
                for (int nt = 0; nt < 8; nt++) {
                    mma_bf16(acc[mt][nt], ah[mt], bhv[nt][0], bhv[nt][1]);
                    mma_bf16(acc[mt][nt], ah[mt], blv[nt][0], blv[nt][1]);
                    mma_bf16(acc[mt][nt], al[mt], bhv[nt][0], bhv[nt][1]);
                }
        }
        __syncthreads();
    }

    // Epilogue: add bias, write fp32 to g_qkv
    const int crow = lane >> 2;
    const int ccol = (lane & 3) * 2;
#pragma unroll
    for (int mt = 0; mt < 2; mt++) {
        int r0 = bm + warp_m + mt * 16 + crow;
#pragma unroll
        for (int nt = 0; nt < 8; nt++) {
            int col = bn + warp_n + nt * 8 + ccol;
            float b0 = bias[col], b1 = bias[col + 1];
            float2 v0 = make_float2(acc[mt][nt][0] + b0, acc[mt][nt][1] + b1);
            float2 v1 = make_float2(acc[mt][nt][2] + b0, acc[mt][nt][3] + b1);
            *(float2*)(g_qkv + (size_t)r0 * C3 + col) = v0;
            *(float2*)(g_qkv + (size_t)(r0 + 8) * C3 + col) = v1;
        }
    }
}

// ---------------------------------------------------------------------------
// Kernel 2: causal relu-attention (unchanged from R1, known-good)
// ---------------------------------------------------------------------------
#define ST 68
#define ATTN_SMEM (3 * 64 * ST * 4)

__global__ __launch_bounds__(256) void attn_kernel(float* __restrict__ out)
{
    extern __shared__ float smf[];
    float* Qt  = smf;
    float* KSt = smf + 64 * ST;
    float* Vs  = smf + 2 * 64 * ST;

    const int tid = threadIdx.x;
    const int qb  = blockIdx.x;
    const int bh  = blockIdx.y;
    const int b   = bh / NH;
    const int h   = bh % NH;
    const int tx  = tid & 15;
    const int ty  = tid >> 4;

    const float* base = g_qkv + (size_t)b * T_SEQ * C3 + h * HS;

#pragma unroll
    for (int l = 0; l < 4; l++) {
        int idx = tid + l * 256;
        int r   = idx >> 4;
        int c   = (idx & 15) << 2;
        float4 v = *(const float4*)(base + (size_t)(qb * 64 + r) * C3 + c);
        Qt[(c + 0) * ST + r] = v.x;
        Qt[(c + 1) * ST + r] = v.y;
        Qt[(c + 2) * ST + r] = v.z;
        Qt[(c + 3) * ST + r] = v.w;
    }

    float y[4][4];
#pragma unroll
    for (int i = 0; i < 4; i++)
#pragma unroll
        for (int j = 0; j < 4; j++) y[i][j] = 0.f;

    for (int kb = 0; kb <= qb; kb++) {
        __syncthreads();
#pragma unroll
        for (int l = 0; l < 4; l++) {
            int idx = tid + l * 256;
            int r   = idx >> 4;
            int c   = (idx & 15) << 2;
            const float* kp = base + (size_t)(kb * 64 + r) * C3 + C_DIM + c;
            float4 kv = *(const float4*)kp;
            KSt[(c + 0) * ST + r] = kv.x;
            KSt[(c + 1) * ST + r] = kv.y;
            KSt[(c + 2) * ST + r] = kv.z;
            KSt[(c + 3) * ST + r] = kv.w;
            float4 vv = *(const float4*)(kp + C_DIM);
            *(float4*)(&Vs[r * ST + c]) = vv;
        }
        __syncthreads();

        float s[4][4];
#pragma unroll
        for (int i = 0; i < 4; i++)
#pragma unroll
            for (int j = 0; j < 4; j++) s[i][j] = 0.f;

#pragma unroll 8
        for (int d = 0; d < 64; d++) {
            float4 qa = *(float4*)(&Qt[d * ST + ty * 4]);
            float4 ka = *(float4*)(&KSt[d * ST + tx * 4]);
            float a[4] = {qa.x, qa.y, qa.z, qa.w};
            float bb[4] = {ka.x, ka.y, ka.z, ka.w};
#pragma unroll
            for (int i = 0; i < 4; i++)
#pragma unroll
                for (int j = 0; j < 4; j++)
                    s[i][j] = fmaf(a[i], bb[j], s[i][j]);
        }
        __syncthreads();

#pragma unroll
        for (int j = 0; j < 4; j++) {
            int tk = kb * 64 + tx * 4 + j;
            float tmp[4];
#pragma unroll
            for (int i = 0; i < 4; i++) {
                int tq = qb * 64 + ty * 4 + i;
                float val = fmaxf(s[i][j] * SCALE_F, 0.f);
                if (tk > tq) val = 0.f;
                tmp[i] = val;
            }
            float4 sv = make_float4(tmp[0], tmp[1], tmp[2], tmp[3]);
            *(float4*)(&KSt[(tx * 4 + j) * ST + ty * 4]) = sv;
        }
        __syncthreads();

#pragma unroll 8
        for (int c = 0; c < 64; c++) {
            float4 sa = *(float4*)(&KSt[c * ST + ty * 4]);
            float4 va = *(float4*)(&Vs[c * ST + tx * 4]);
            float a[4] = {sa.x, sa.y, sa.z, sa.w};
            float bb[4] = {va.x, va.y, va.z, va.w};
#pragma unroll
            for (int i = 0; i < 4; i++)
#pragma unroll
                for (int j = 0; j < 4; j++)
                    y[i][j] = fmaf(a[i], bb[j], y[i][j]);
        }
    }

#pragma unroll
    for (int i = 0; i < 4; i++) {
        int t = qb * 64 + ty * 4 + i;
        float4 v = make_float4(y[i][0], y[i][1], y[i][2], y[i][3]);
        *(float4*)(out + ((size_t)b * T_SEQ + t) * C_DIM + h * HS + tx * 4) = v;
    }
}

// ---------------------------------------------------------------------------
extern "C" void kernel_launch(void* const* d_in, const int* in_sizes, int n_in,
                              void* d_out, int out_size)
{
    const float* x    = (const float*)d_in[0];
    const float* W    = (const float*)d_in[1];
    const float* bias = (const float*)d_in[2];
    float* out        = (float*)d_out;

    prep_x_kernel<<<(M_ROWS * C_DIM + 255) / 256, 256>>>(x);
    prep_w_kernel<<<dim3(C3 / 32, C_DIM / 32), dim3(32, 8)>>>(W);

    cudaFuncSetAttribute(qkv_mma_kernel,
                         cudaFuncAttributeMaxDynamicSharedMemorySize, GEMM_SMEM);
    qkv_mma_kernel<<<dim3(C3 / 128, M_ROWS / 128), 256, GEMM_SMEM>>>(bias);

    cudaFuncSetAttribute(attn_kernel,
                         cudaFuncAttributeMaxDynamicSharedMemorySize, ATTN_SMEM);
    attn_kernel<<<dim3(16, B_SZ * NH), 256, ATTN_SMEM>>>(out);
}

// round 4
// speedup vs baseline: 2.5616x; 1.7277x over previous
#include <cuda_runtime.h>
#include <cuda_bf16.h>
#include <cstdint>

#define B_SZ   8
#define T_SEQ  1024
#define C_DIM  768
#define C3     2304
#define NH     12
#define HS     64
#define SCALE_F 0.125f
#define M_ROWS (B_SZ * T_SEQ)       /* 8192 */
#define NBH    (B_SZ * NH)          /* 96 */

// bf16 hi/lo splits of x [8192,768] and W^T [2304,768] (K-contiguous)
__device__ __align__(16) __nv_bfloat16 g_xhi[(size_t)M_ROWS * C_DIM];
__device__ __align__(16) __nv_bfloat16 g_xlo[(size_t)M_ROWS * C_DIM];
__device__ __align__(16) __nv_bfloat16 g_wthi[(size_t)C3 * C_DIM];
__device__ __align__(16) __nv_bfloat16 g_wtlo[(size_t)C3 * C_DIM];
// head-separated QKV outputs, bf16 hi/lo: [bh, t, 64]
#define QKV_ELEMS ((size_t)NBH * T_SEQ * HS)
__device__ __align__(16) __nv_bfloat16 g_q_hi[QKV_ELEMS], g_q_lo[QKV_ELEMS];
__device__ __align__(16) __nv_bfloat16 g_k_hi[QKV_ELEMS], g_k_lo[QKV_ELEMS];
__device__ __align__(16) __nv_bfloat16 g_v_hi[QKV_ELEMS], g_v_lo[QKV_ELEMS];

// ---------------------------------------------------------------------------
// helpers
// ---------------------------------------------------------------------------
__device__ __forceinline__ uint32_t smem_u32(const void* p) {
    uint32_t a;
    asm("{ .reg .u64 t; cvta.to.shared.u64 t, %1; cvt.u32.u64 %0, t; }"
        : "=r"(a) : "l"(p));
    return a;
}
#define SWZ128(off) ((off) ^ (((off) >> 3) & 0x70))

__device__ __forceinline__ void cp_async16(uint32_t saddr, const void* gaddr) {
    asm volatile("cp.async.cg.shared.global [%0], [%1], 16;"
                 :: "r"(saddr), "l"(gaddr) : "memory");
}
__device__ __forceinline__ void cp_commit() {
    asm volatile("cp.async.commit_group;" ::: "memory");
}
template <int N>
__device__ __forceinline__ void cp_wait() {
    asm volatile("cp.async.wait_group %0;" :: "n"(N) : "memory");
}
__device__ __forceinline__ void ldm_x4(uint32_t* r, uint32_t addr) {
    asm volatile("ldmatrix.sync.aligned.m8n8.x4.shared.b16 {%0,%1,%2,%3}, [%4];"
                 : "=r"(r[0]), "=r"(r[1]), "=r"(r[2]), "=r"(r[3]) : "r"(addr));
}
__device__ __forceinline__ void ldm_x4_t(uint32_t* r, uint32_t addr) {
    asm volatile("ldmatrix.sync.aligned.m8n8.x4.trans.shared.b16 {%0,%1,%2,%3}, [%4];"
                 : "=r"(r[0]), "=r"(r[1]), "=r"(r[2]), "=r"(r[3]) : "r"(addr));
}
__device__ __forceinline__ void mma_bf16(float* c, const uint32_t* a,
                                         const uint32_t b0, const uint32_t b1) {
    asm volatile(
        "mma.sync.aligned.m16n8k16.row.col.f32.bf16.bf16.f32 "
        "{%0,%1,%2,%3}, {%4,%5,%6,%7}, {%8,%9}, {%0,%1,%2,%3};"
        : "+f"(c[0]), "+f"(c[1]), "+f"(c[2]), "+f"(c[3])
        : "r"(a[0]), "r"(a[1]), "r"(a[2]), "r"(a[3]), "r"(b0), "r"(b1));
}
// pack two fp32 -> bf16x2 (v0 in low half, v1 in high half)
__device__ __forceinline__ uint32_t pack_bf16x2(float v0, float v1) {
    uint32_t p;
    asm("cvt.rn.bf16x2.f32 %0, %1, %2;" : "=r"(p) : "f"(v1), "f"(v0));
    return p;
}

// ---------------------------------------------------------------------------
// Prep kernels: bf16 hi/lo split of x; transpose+split of W
// ---------------------------------------------------------------------------
__global__ void prep_x_kernel(const float* __restrict__ x) {
    int i = blockIdx.x * blockDim.x + threadIdx.x;
    if (i >= M_ROWS * C_DIM) return;
    float v = x[i];
    __nv_bfloat16 hi = __float2bfloat16(v);
    g_xhi[i] = hi;
    g_xlo[i] = __float2bfloat16(v - __bfloat162float(hi));
}

__global__ void prep_w_kernel(const float* __restrict__ W) {
    __shared__ float t[32][33];
    int n0 = blockIdx.x * 32, k0 = blockIdx.y * 32;
    int tx = threadIdx.x, ty = threadIdx.y;
#pragma unroll
    for (int j = 0; j < 4; j++)
        t[ty + 8 * j][tx] = W[(size_t)(k0 + ty + 8 * j) * C3 + n0 + tx];
    __syncthreads();
#pragma unroll
    for (int j = 0; j < 4; j++) {
        float v = t[tx][ty + 8 * j];
        __nv_bfloat16 hi = __float2bfloat16(v);
        size_t o = (size_t)(n0 + ty + 8 * j) * C_DIM + k0 + tx;
        g_wthi[o] = hi;
        g_wtlo[o] = __float2bfloat16(v - __bfloat162float(hi));
    }
}

// ---------------------------------------------------------------------------
// Kernel 1: QKV projection via mma.sync bf16 3-term split.
// Block tile 128x128, K-chunk 64, 8 warps, double-buffered.
// Epilogue writes Q/K/V bf16 hi/lo in [bh, t, 64] layout.
// ---------------------------------------------------------------------------
#define BK       64
#define NCHUNK   (C_DIM / BK)          /* 12 */
#define TILE_B   (128 * 128)           /* 16 KB */
#define STAGE_B  (4 * TILE_B)
#define GEMM_SMEM (2 * STAGE_B)        /* 128 KB */

__device__ __forceinline__ void load_stage(uint32_t sbase, int bm, int bn,
                                           int k0, int tid)
{
#pragma unroll
    for (int i = 0; i < 4; i++) {
        int lin = i * 256 + tid;
        int r   = lin >> 3;
        int cb  = (lin & 7) * 16;
        uint32_t sw = SWZ128((uint32_t)(r * 128 + cb));
        const char* ax = (const char*)(g_xhi + (size_t)(bm + r) * C_DIM + k0) + cb;
        cp_async16(sbase + 0 * TILE_B + sw, ax);
        const char* al = (const char*)(g_xlo + (size_t)(bm + r) * C_DIM + k0) + cb;
        cp_async16(sbase + 1 * TILE_B + sw, al);
        const char* bh = (const char*)(g_wthi + (size_t)(bn + r) * C_DIM + k0) + cb;
        cp_async16(sbase + 2 * TILE_B + sw, bh);
        const char* bl = (const char*)(g_wtlo + (size_t)(bn + r) * C_DIM + k0) + cb;
        cp_async16(sbase + 3 * TILE_B + sw, bl);
    }
    cp_commit();
}

__global__ __launch_bounds__(256, 1) void qkv_mma_kernel(const float* __restrict__ bias)
{
    extern __shared__ char sm[];
    const uint32_t sbase = smem_u32(sm);

    const int tid  = threadIdx.x;
    const int wid  = tid >> 5;
    const int lane = tid & 31;
    const int bn   = blockIdx.x * 128;
    const int bm   = blockIdx.y * 128;
    const int warp_m = (wid & 3) * 32;
    const int warp_n = (wid >> 2) * 64;
    const int ldrow   = lane & 15;
    const int ldchunk = (lane >> 4) * 16;

    float acc[2][8][4];
#pragma unroll
    for (int mt = 0; mt < 2; mt++)
#pragma unroll
        for (int nt = 0; nt < 8; nt++)
#pragma unroll
            for (int q = 0; q < 4; q++) acc[mt][nt][q] = 0.f;

    load_stage(sbase, bm, bn, 0, tid);

    for (int ch = 0; ch < NCHUNK; ch++) {
        const uint32_t sstage = sbase + (uint32_t)(ch & 1) * STAGE_B;
        if (ch + 1 < NCHUNK) {
            load_stage(sbase + (uint32_t)((ch + 1) & 1) * STAGE_B,
                       bm, bn, (ch + 1) * BK, tid);
            cp_wait<1>();
        } else {
            cp_wait<0>();
        }
        __syncthreads();

#pragma unroll
        for (int ks = 0; ks < 4; ks++) {
            const int kb = ks * 32 + ldchunk;
            uint32_t ah[2][4], al[2][4];
#pragma unroll
            for (int mt = 0; mt < 2; mt++) {
                uint32_t off = SWZ128((uint32_t)((warp_m + mt * 16 + ldrow) * 128 + kb));
                ldm_x4(ah[mt], sstage + 0 * TILE_B + off);
                ldm_x4(al[mt], sstage + 1 * TILE_B + off);
            }
            uint32_t bhv[8][2], blv[8][2];
#pragma unroll
            for (int np = 0; np < 4; np++) {
                uint32_t off = SWZ128((uint32_t)((warp_n + np * 16 + ldrow) * 128 + kb));
                uint32_t r[4];
                ldm_x4(r, sstage + 2 * TILE_B + off);
                bhv[2 * np][0] = r[0]; bhv[2 * np][1] = r[2];
                bhv[2 * np + 1][0] = r[1]; bhv[2 * np + 1][1] = r[3];
                ldm_x4(r, sstage + 3 * TILE_B + off);
                blv[2 * np][0] = r[0]; blv[2 * np][1] = r[2];
                blv[2 * np + 1][0] = r[1]; blv[2 * np + 1][1] = r[3];
            }
#pragma unroll
            for (int mt = 0; mt < 2; mt++)
#pragma unroll
                for (int nt = 0; nt < 8; nt++) {
                    mma_bf16(acc[mt][nt], ah[mt], bhv[nt][0], bhv[nt][1]);
                    mma_bf16(acc[mt][nt], ah[mt], blv[nt][0], blv[nt][1]);
                    mma_bf16(acc[mt][nt], al[mt], bhv[nt][0], bhv[nt][1]);
                }
        }
        __syncthreads();
    }

    // Epilogue: add bias, split hi/lo, write head-separated bf16 layouts
    const int crow = lane >> 2;
    const int ccol = (lane & 3) * 2;
#pragma unroll
    for (int mt = 0; mt < 2; mt++) {
        int r0 = bm + warp_m + mt * 16 + crow;
#pragma unroll
        for (int nt = 0; nt < 8; nt++) {
            int col   = bn + warp_n + nt * 8 + ccol;
            int which = col / C_DIM;
            int hh    = (col % C_DIM) / HS;
            int dd    = col % HS;
            float2 bb = *(const float2*)(bias + col);
            __nv_bfloat16 *dhi, *dlo;
            if (which == 0)      { dhi = g_q_hi; dlo = g_q_lo; }
            else if (which == 1) { dhi = g_k_hi; dlo = g_k_lo; }
            else                 { dhi = g_v_hi; dlo = g_v_lo; }
#pragma unroll
            for (int p = 0; p < 2; p++) {
                int r = r0 + p * 8;
                float v0 = acc[mt][nt][2 * p + 0] + bb.x;
                float v1 = acc[mt][nt][2 * p + 1] + bb.y;
                uint32_t hi = pack_bf16x2(v0, v1);
                __nv_bfloat162 hp = *reinterpret_cast<__nv_bfloat162*>(&hi);
                uint32_t lo = pack_bf16x2(v0 - __low2float(hp), v1 - __high2float(hp));
                int bidx = r >> 10, t = r & 1023;
                size_t off = (((size_t)(bidx * NH + hh)) * T_SEQ + t) * HS + dd;
                *(uint32_t*)(dhi + off) = hi;
                *(uint32_t*)(dlo + off) = lo;
            }
        }
    }
}

// ---------------------------------------------------------------------------
// Kernel 2: causal relu-attention via mma.sync, FA2-style.
// Block = (bh, 128 q-rows); 8 warps x 16 q-rows; kv-tile 64, double-buffered.
// ---------------------------------------------------------------------------
#define AQ_HI   0
#define AQ_LO   16384
#define ASTG    32768
#define ASTG_SZ 32768
#define AK_HI   0
#define AK_LO   8192
#define AV_HI   16384
#define AV_LO   24576
#define ATTN_SMEM (ASTG + 2 * ASTG_SZ)   /* 96 KB */

__device__ __forceinline__ void load_kv_stage(uint32_t dst, int bh, int kv0, int tid) {
#pragma unroll
    for (int i = 0; i < 8; i++) {
        int lin = i * 256 + tid;           // 0..2047
        int buf = lin >> 9;                // 0:Khi 1:Klo 2:Vhi 3:Vlo
        int idx = lin & 511;
        int r = idx >> 3, cb = (idx & 7) * 16;
        uint32_t sw = SWZ128((uint32_t)(r * 128 + cb));
        const __nv_bfloat16* src = (buf == 0) ? g_k_hi : (buf == 1) ? g_k_lo
                                 : (buf == 2) ? g_v_hi : g_v_lo;
        cp_async16(dst + buf * 8192 + sw,
                   (const char*)(src + ((size_t)bh * T_SEQ + kv0 + r) * HS) + cb);
    }
    cp_commit();
}

__global__ __launch_bounds__(256, 2) void attn_mma_kernel(float* __restrict__ out)
{
    extern __shared__ char sm[];
    const uint32_t sb = smem_u32(sm);
    const int tid = threadIdx.x, wid = tid >> 5, lane = tid & 31;
    const int qt = blockIdx.x, bh = blockIdx.y;
    const int b = bh / NH, h = bh % NH;

    // Q tile load (128 rows), hi & lo
#pragma unroll
    for (int i = 0; i < 8; i++) {
        int lin = i * 256 + tid;           // 0..2047
        int buf = lin >> 10;               // 0 hi, 1 lo
        int idx = lin & 1023;
        int r = idx >> 3, cb = (idx & 7) * 16;
        uint32_t sw = SWZ128((uint32_t)(r * 128 + cb));
        const __nv_bfloat16* src = buf ? g_q_lo : g_q_hi;
        cp_async16(sb + (buf ? AQ_LO : AQ_HI) + sw,
                   (const char*)(src + ((size_t)bh * T_SEQ + qt * 128 + r) * HS) + cb);
    }
    cp_commit();
    load_kv_stage(sb + ASTG, bh, 0, tid);

    float accY[8][4];
#pragma unroll
    for (int nt = 0; nt < 8; nt++)
#pragma unroll
        for (int q = 0; q < 4; q++) accY[nt][q] = 0.f;

    const int niter = 2 * qt + 2;
    for (int it = 0; it < niter; it++) {
        __syncthreads();   // prior-iteration reads done before overwriting buffer
        if (it + 1 < niter) {
            load_kv_stage(sb + ASTG + (uint32_t)((it + 1) & 1) * ASTG_SZ,
                          bh, (it + 1) * 64, tid);
            cp_wait<1>();
        } else {
            cp_wait<0>();
        }
        __syncthreads();

        const uint32_t stg = sb + ASTG + (uint32_t)(it & 1) * ASTG_SZ;

        // ---- S = Q K^T (3-term hi/lo) ----
        float s[8][4];
#pragma unroll
        for (int nt = 0; nt < 8; nt++)
#pragma unroll
            for (int q = 0; q < 4; q++) s[nt][q] = 0.f;

#pragma unroll
        for (int ks = 0; ks < 4; ks++) {
            uint32_t qoff = SWZ128((uint32_t)((wid * 16 + (lane & 15)) * 128
                                              + ks * 32 + (lane >> 4) * 16));
            uint32_t qh[4], ql[4];
            ldm_x4(qh, sb + AQ_HI + qoff);
            ldm_x4(ql, sb + AQ_LO + qoff);
            uint32_t kh[8][2], kl[8][2];
#pragma unroll
            for (int np = 0; np < 4; np++) {
                uint32_t koff = SWZ128((uint32_t)((np * 16 + (lane & 15)) * 128
                                                  + ks * 32 + (lane >> 4) * 16));
                uint32_t r[4];
                ldm_x4(r, stg + AK_HI + koff);
                kh[2 * np][0] = r[0]; kh[2 * np][1] = r[2];
                kh[2 * np + 1][0] = r[1]; kh[2 * np + 1][1] = r[3];
                ldm_x4(r, stg + AK_LO + koff);
                kl[2 * np][0] = r[0]; kl[2 * np][1] = r[2];
                kl[2 * np + 1][0] = r[1]; kl[2 * np + 1][1] = r[3];
            }
#pragma unroll
            for (int nt = 0; nt < 8; nt++) {
                mma_bf16(s[nt], qh, kh[nt][0], kh[nt][1]);
                mma_bf16(s[nt], qh, kl[nt][0], kl[nt][1]);
                mma_bf16(s[nt], ql, kh[nt][0], kh[nt][1]);
            }
        }

        // ---- mask + relu + scale; split S into bf16 hi/lo A-fragments ----
        const int q0  = qt * 128 + wid * 16 + (lane >> 2);
        const int kvb = it * 64 + (lane & 3) * 2;
        uint32_t ahi[4][4], alo[4][4];     // [k-step][frag reg]
#pragma unroll
        for (int nt = 0; nt < 8; nt++) {
            int kv0 = kvb + nt * 8;
#pragma unroll
            for (int p = 0; p < 2; p++) {
                int qq = q0 + p * 8;
                float v0 = (kv0     <= qq) ? fmaxf(s[nt][2 * p + 0] * SCALE_F, 0.f) : 0.f;
                float v1 = (kv0 + 1 <= qq) ? fmaxf(s[nt][2 * p + 1] * SCALE_F, 0.f) : 0.f;
                uint32_t hi = pack_bf16x2(v0, v1);
                __nv_bfloat162 hp = *reinterpret_cast<__nv_bfloat162*>(&hi);
                uint32_t lo = pack_bf16x2(v0 - __low2float(hp), v1 - __high2float(hp));
                ahi[nt >> 1][(nt & 1) * 2 + p] = hi;
                alo[nt >> 1][(nt & 1) * 2 + p] = lo;
            }
        }

        // ---- Y += S V (3-term), V via ldmatrix.trans ----
#pragma unroll
        for (int ks = 0; ks < 4; ks++) {
#pragma unroll
            for (int np = 0; np < 4; np++) {
                uint32_t voff = SWZ128((uint32_t)(
                    (ks * 16 + (lane & 7) + ((lane >> 4) & 1) * 8) * 128
                    + np * 32 + ((lane >> 3) & 1) * 16));
                uint32_t vh[4], vl[4];
                ldm_x4_t(vh, stg + AV_HI + voff);
                ldm_x4_t(vl, stg + AV_LO + voff);
                mma_bf16(accY[2 * np],     ahi[ks], vh[0], vh[2]);
                mma_bf16(accY[2 * np],     ahi[ks], vl[0], vl[2]);
                mma_bf16(accY[2 * np],     alo[ks], vh[0], vh[2]);
                mma_bf16(accY[2 * np + 1], ahi[ks], vh[1], vh[3]);
                mma_bf16(accY[2 * np + 1], ahi[ks], vl[1], vl[3]);
                mma_bf16(accY[2 * np + 1], alo[ks], vh[1], vh[3]);
            }
        }
    }

    // ---- write out[b, t, h*64 + d] ----
    const int q0 = qt * 128 + wid * 16 + (lane >> 2);
#pragma unroll
    for (int nt = 0; nt < 8; nt++) {
        int col = h * HS + nt * 8 + (lane & 3) * 2;
        *(float2*)(out + ((size_t)b * T_SEQ + q0) * C_DIM + col) =
            make_float2(accY[nt][0], accY[nt][1]);
        *(float2*)(out + ((size_t)b * T_SEQ + q0 + 8) * C_DIM + col) =
            make_float2(accY[nt][2], accY[nt][3]);
    }
}

// ---------------------------------------------------------------------------
extern "C" void kernel_launch(void* const* d_in, const int* in_sizes, int n_in,
                              void* d_out, int out_size)
{
    const float* x    = (const float*)d_in[0];
    const float* W    = (const float*)d_in[1];
    const float* bias = (const float*)d_in[2];
    float* out        = (float*)d_out;

    prep_x_kernel<<<(M_ROWS * C_DIM + 255) / 256, 256>>>(x);
    prep_w_kernel<<<dim3(C3 / 32, C_DIM / 32), dim3(32, 8)>>>(W);

    cudaFuncSetAttribute(qkv_mma_kernel,
                         cudaFuncAttributeMaxDynamicSharedMemorySize, GEMM_SMEM);
    qkv_mma_kernel<<<dim3(C3 / 128, M_ROWS / 128), 256, GEMM_SMEM>>>(bias);

    cudaFuncSetAttribute(attn_mma_kernel,
                         cudaFuncAttributeMaxDynamicSharedMemorySize, ATTN_SMEM);
    attn_mma_kernel<<<dim3(8, NBH), 256, ATTN_SMEM>>>(out);
}

// round 5
// speedup vs baseline: 6.4456x; 2.5162x over previous
#include <cuda_runtime.h>
#include <cuda_fp16.h>
#include <cstdint>

#define B_SZ   8
#define T_SEQ  1024
#define C_DIM  768
#define C3     2304
#define NH     12
#define HS     64
#define SCALE_F 0.125f
#define M_ROWS (B_SZ * T_SEQ)       /* 8192 */
#define NBH    (B_SZ * NH)          /* 96 */

// fp16 operands: x [8192,768], W^T [2304,768] (K-contiguous)
__device__ __align__(16) __half g_xh[(size_t)M_ROWS * C_DIM];
__device__ __align__(16) __half g_wth[(size_t)C3 * C_DIM];
// head-separated QKV outputs, fp16: [bh, t, 64]
#define QKV_ELEMS ((size_t)NBH * T_SEQ * HS)
__device__ __align__(16) __half g_q[QKV_ELEMS], g_k[QKV_ELEMS], g_v[QKV_ELEMS];

// ---------------------------------------------------------------------------
// helpers
// ---------------------------------------------------------------------------
__device__ __forceinline__ uint32_t smem_u32(const void* p) {
    uint32_t a;
    asm("{ .reg .u64 t; cvta.to.shared.u64 t, %1; cvt.u32.u64 %0, t; }"
        : "=r"(a) : "l"(p));
    return a;
}
#define SWZ128(off) ((off) ^ (((off) >> 3) & 0x70))

__device__ __forceinline__ void cp_async16(uint32_t saddr, const void* gaddr) {
    asm volatile("cp.async.cg.shared.global [%0], [%1], 16;"
                 :: "r"(saddr), "l"(gaddr) : "memory");
}
__device__ __forceinline__ void cp_commit() {
    asm volatile("cp.async.commit_group;" ::: "memory");
}
template <int N>
__device__ __forceinline__ void cp_wait() {
    asm volatile("cp.async.wait_group %0;" :: "n"(N) : "memory");
}
__device__ __forceinline__ void ldm_x4(uint32_t* r, uint32_t addr) {
    asm volatile("ldmatrix.sync.aligned.m8n8.x4.shared.b16 {%0,%1,%2,%3}, [%4];"
                 : "=r"(r[0]), "=r"(r[1]), "=r"(r[2]), "=r"(r[3]) : "r"(addr));
}
__device__ __forceinline__ void ldm_x4_t(uint32_t* r, uint32_t addr) {
    asm volatile("ldmatrix.sync.aligned.m8n8.x4.trans.shared.b16 {%0,%1,%2,%3}, [%4];"
                 : "=r"(r[0]), "=r"(r[1]), "=r"(r[2]), "=r"(r[3]) : "r"(addr));
}
__device__ __forceinline__ void mma_f16(float* c, const uint32_t* a,
                                        const uint32_t b0, const uint32_t b1) {
    asm volatile(
        "mma.sync.aligned.m16n8k16.row.col.f32.f16.f16.f32 "
        "{%0,%1,%2,%3}, {%4,%5,%6,%7}, {%8,%9}, {%0,%1,%2,%3};"
        : "+f"(c[0]), "+f"(c[1]), "+f"(c[2]), "+f"(c[3])
        : "r"(a[0]), "r"(a[1]), "r"(a[2]), "r"(a[3]), "r"(b0), "r"(b1));
}
__device__ __forceinline__ uint32_t pack_f16x2(float v0, float v1) {
    __half2 h = __floats2half2_rn(v0, v1);   // v0 -> low
    return *reinterpret_cast<uint32_t*>(&h);
}

// ---------------------------------------------------------------------------
// Prep kernels: fp16 convert of x; transpose+convert of W
// ---------------------------------------------------------------------------
__global__ void prep_x_kernel(const float* __restrict__ x) {
    int i = blockIdx.x * blockDim.x + threadIdx.x;
    if (i >= M_ROWS * C_DIM) return;
    g_xh[i] = __float2half(x[i]);
}

__global__ void prep_w_kernel(const float* __restrict__ W) {
    __shared__ float t[32][33];
    int n0 = blockIdx.x * 32, k0 = blockIdx.y * 32;
    int tx = threadIdx.x, ty = threadIdx.y;
#pragma unroll
    for (int j = 0; j < 4; j++)
        t[ty + 8 * j][tx] = W[(size_t)(k0 + ty + 8 * j) * C3 + n0 + tx];
    __syncthreads();
#pragma unroll
    for (int j = 0; j < 4; j++)
        g_wth[(size_t)(n0 + ty + 8 * j) * C_DIM + k0 + tx] = __float2half(t[tx][ty + 8 * j]);
}

// ---------------------------------------------------------------------------
// Kernel 1: QKV projection, single-pass fp16 mma.sync.
// Block tile 128x128, K-chunk 64, 8 warps (warp 32x64), double-buffered.
// ---------------------------------------------------------------------------
#define BK       64
#define NCHUNK   (C_DIM / BK)          /* 12 */
#define TILE_B   (128 * 128)           /* 128 rows x 128 bytes = 16 KB */
#define STAGE_B  (2 * TILE_B)          /* A, B */
#define GEMM_SMEM (2 * STAGE_B)        /* 64 KB */

__device__ __forceinline__ void load_stage(uint32_t sbase, int bm, int bn,
                                           int k0, int tid)
{
#pragma unroll
    for (int i = 0; i < 8; i++) {
        int lin = i * 256 + tid;          // 0..2047
        int buf = lin >> 10;              // 0:A 1:B
        int idx = lin & 1023;
        int r   = idx >> 3;               // row 0..127
        int cb  = (idx & 7) * 16;         // byte col 0..112
        uint32_t sw = SWZ128((uint32_t)(r * 128 + cb));
        const char* src = buf
            ? (const char*)(g_wth + (size_t)(bn + r) * C_DIM + k0) + cb
            : (const char*)(g_xh  + (size_t)(bm + r) * C_DIM + k0) + cb;
        cp_async16(sbase + buf * TILE_B + sw, src);
    }
    cp_commit();
}

__global__ __launch_bounds__(256, 2) void qkv_mma_kernel(const float* __restrict__ bias)
{
    extern __shared__ char sm[];
    const uint32_t sbase = smem_u32(sm);

    const int tid  = threadIdx.x;
    const int wid  = tid >> 5;
    const int lane = tid & 31;
    const int bn   = blockIdx.x * 128;
    const int bm   = blockIdx.y * 128;
    const int warp_m = (wid & 3) * 32;
    const int warp_n = (wid >> 2) * 64;
    const int ldrow   = lane & 15;
    const int ldchunk = (lane >> 4) * 16;

    float acc[2][8][4];
#pragma unroll
    for (int mt = 0; mt < 2; mt++)
#pragma unroll
        for (int nt = 0; nt < 8; nt++)
#pragma unroll
            for (int q = 0; q < 4; q++) acc[mt][nt][q] = 0.f;

    load_stage(sbase, bm, bn, 0, tid);

    for (int ch = 0; ch < NCHUNK; ch++) {
        const uint32_t sstage = sbase + (uint32_t)(ch & 1) * STAGE_B;
        if (ch + 1 < NCHUNK) {
            load_stage(sbase + (uint32_t)((ch + 1) & 1) * STAGE_B,
                       bm, bn, (ch + 1) * BK, tid);
            cp_wait<1>();
        } else {
            cp_wait<0>();
        }
        __syncthreads();

#pragma unroll
        for (int ks = 0; ks < 4; ks++) {
            const int kb = ks * 32 + ldchunk;
            uint32_t a[2][4];
#pragma unroll
            for (int mt = 0; mt < 2; mt++) {
                uint32_t off = SWZ128((uint32_t)((warp_m + mt * 16 + ldrow) * 128 + kb));
                ldm_x4(a[mt], sstage + off);
            }
            uint32_t bv[8][2];
#pragma unroll
            for (int np = 0; np < 4; np++) {
                uint32_t off = SWZ128((uint32_t)((warp_n + np * 16 + ldrow) * 128 + kb));
                uint32_t r[4];
                ldm_x4(r, sstage + TILE_B + off);
                bv[2 * np][0] = r[0]; bv[2 * np][1] = r[2];
                bv[2 * np + 1][0] = r[1]; bv[2 * np + 1][1] = r[3];
            }
#pragma unroll
            for (int mt = 0; mt < 2; mt++)
#pragma unroll
                for (int nt = 0; nt < 8; nt++)
                    mma_f16(acc[mt][nt], a[mt], bv[nt][0], bv[nt][1]);
        }
        __syncthreads();
    }

    // Epilogue: add bias, write head-separated fp16 q/k/v
    const int crow = lane >> 2;
    const int ccol = (lane & 3) * 2;
#pragma unroll
    for (int mt = 0; mt < 2; mt++) {
        int r0 = bm + warp_m + mt * 16 + crow;
#pragma unroll
        for (int nt = 0; nt < 8; nt++) {
            int col   = bn + warp_n + nt * 8 + ccol;
            int which = col / C_DIM;
            int hh    = (col % C_DIM) / HS;
            int dd    = col % HS;
            float2 bb = *(const float2*)(bias + col);
            __half* dst = (which == 0) ? g_q : (which == 1) ? g_k : g_v;
#pragma unroll
            for (int p = 0; p < 2; p++) {
                int r = r0 + p * 8;
                uint32_t hv = pack_f16x2(acc[mt][nt][2 * p + 0] + bb.x,
                                         acc[mt][nt][2 * p + 1] + bb.y);
                int bidx = r >> 10, t = r & 1023;
                size_t off = (((size_t)(bidx * NH + hh)) * T_SEQ + t) * HS + dd;
                *(uint32_t*)(dst + off) = hv;
            }
        }
    }
}

// ---------------------------------------------------------------------------
// Kernel 2: causal relu-attention, single-pass fp16 mma.sync, FA2-style.
// Block = (bh, 128 q-rows); 8 warps x 16 q-rows; kv-tile 64, double-buffered.
// ---------------------------------------------------------------------------
#define AQ      0
#define ASTG    16384
#define ASTG_SZ 16384                  /* K 8KB + V 8KB */
#define AK      0
#define AV      8192
#define ATTN_SMEM (ASTG + 2 * ASTG_SZ) /* 48 KB */

__device__ __forceinline__ void load_kv_stage(uint32_t dst, int bh, int kv0, int tid) {
#pragma unroll
    for (int i = 0; i < 4; i++) {
        int lin = i * 256 + tid;          // 0..1023
        int buf = lin >> 9;               // 0:K 1:V
        int idx = lin & 511;
        int r = idx >> 3, cb = (idx & 7) * 16;
        uint32_t sw = SWZ128((uint32_t)(r * 128 + cb));
        const __half* src = buf ? g_v : g_k;
        cp_async16(dst + buf * 8192 + sw,
                   (const char*)(src + ((size_t)bh * T_SEQ + kv0 + r) * HS) + cb);
    }
    cp_commit();
}

__global__ __launch_bounds__(256, 2) void attn_mma_kernel(float* __restrict__ out)
{
    extern __shared__ char sm[];
    const uint32_t sb = smem_u32(sm);
    const int tid = threadIdx.x, wid = tid >> 5, lane = tid & 31;
    const int qt = gridDim.x - 1 - blockIdx.x;   // heavy blocks first
    const int bh = blockIdx.y;
    const int b = bh / NH, h = bh % NH;

    // Q tile load (128 rows x 64 fp16)
#pragma unroll
    for (int i = 0; i < 4; i++) {
        int idx = i * 256 + tid;          // 0..1023
        int r = idx >> 3, cb = (idx & 7) * 16;
        uint32_t sw = SWZ128((uint32_t)(r * 128 + cb));
        cp_async16(sb + AQ + sw,
                   (const char*)(g_q + ((size_t)bh * T_SEQ + qt * 128 + r) * HS) + cb);
    }
    cp_commit();
    load_kv_stage(sb + ASTG, bh, 0, tid);

    float accY[8][4];
#pragma unroll
    for (int nt = 0; nt < 8; nt++)
#pragma unroll
        for (int q = 0; q < 4; q++) accY[nt][q] = 0.f;

    const int niter = 2 * qt + 2;
    for (int it = 0; it < niter; it++) {
        __syncthreads();
        if (it + 1 < niter) {
            load_kv_stage(sb + ASTG + (uint32_t)((it + 1) & 1) * ASTG_SZ,
                          bh, (it + 1) * 64, tid);
            cp_wait<1>();
        } else {
            cp_wait<0>();
        }
        __syncthreads();

        const uint32_t stg = sb + ASTG + (uint32_t)(it & 1) * ASTG_SZ;

        // ---- S = Q K^T ----
        float s[8][4];
#pragma unroll
        for (int nt = 0; nt < 8; nt++)
#pragma unroll
            for (int q = 0; q < 4; q++) s[nt][q] = 0.f;

#pragma unroll
        for (int ks = 0; ks < 4; ks++) {
            uint32_t qoff = SWZ128((uint32_t)((wid * 16 + (lane & 15)) * 128
                                              + ks * 32 + (lane >> 4) * 16));
            uint32_t qf[4];
            ldm_x4(qf, sb + AQ + qoff);
            uint32_t kf[8][2];
#pragma unroll
            for (int np = 0; np < 4; np++) {
                uint32_t koff = SWZ128((uint32_t)((np * 16 + (lane & 15)) * 128
                                                  + ks * 32 + (lane >> 4) * 16));
                uint32_t r[4];
                ldm_x4(r, stg + AK + koff);
                kf[2 * np][0] = r[0]; kf[2 * np][1] = r[2];
                kf[2 * np + 1][0] = r[1]; kf[2 * np + 1][1] = r[3];
            }
#pragma unroll
            for (int nt = 0; nt < 8; nt++)
                mma_f16(s[nt], qf, kf[nt][0], kf[nt][1]);
        }

        // ---- mask + relu + scale -> fp16 A-fragments ----
        const int q0  = qt * 128 + wid * 16 + (lane >> 2);
        const int kvb = it * 64 + (lane & 3) * 2;
        uint32_t af[4][4];     // [k-step][frag reg]
#pragma unroll
        for (int nt = 0; nt < 8; nt++) {
            int kv0 = kvb + nt * 8;
#pragma unroll
            for (int p = 0; p < 2; p++) {
                int qq = q0 + p * 8;
                float v0 = (kv0     <= qq) ? fmaxf(s[nt][2 * p + 0] * SCALE_F, 0.f) : 0.f;
                float v1 = (kv0 + 1 <= qq) ? fmaxf(s[nt][2 * p + 1] * SCALE_F, 0.f) : 0.f;
                af[nt >> 1][(nt & 1) * 2 + p] = pack_f16x2(v0, v1);
            }
        }

        // ---- Y += S V, V via ldmatrix.trans ----
#pragma unroll
        for (int ks = 0; ks < 4; ks++) {
#pragma unroll
            for (int np = 0; np < 4; np++) {
                uint32_t voff = SWZ128((uint32_t)(
                    (ks * 16 + (lane & 7) + ((lane >> 4) & 1) * 8) * 128
                    + np * 32 + ((lane >> 3) & 1) * 16));
                uint32_t vf[4];
                ldm_x4_t(vf, stg + AV + voff);
                mma_f16(accY[2 * np],     af[ks], vf[0], vf[2]);
                mma_f16(accY[2 * np + 1], af[ks], vf[1], vf[3]);
            }
        }
    }

    // ---- write out[b, t, h*64 + d] ----
    const int q0 = qt * 128 + wid * 16 + (lane >> 2);
#pragma unroll
    for (int nt = 0; nt < 8; nt++) {
        int col = h * HS + nt * 8 + (lane & 3) * 2;
        *(float2*)(out + ((size_t)b * T_SEQ + q0) * C_DIM + col) =
            make_float2(accY[nt][0], accY[nt][1]);
        *(float2*)(out + ((size_t)b * T_SEQ + q0 + 8) * C_DIM + col) =
            make_float2(accY[nt][2], accY[nt][3]);
    }
}

// ---------------------------------------------------------------------------
extern "C" void kernel_launch(void* const* d_in, const int* in_sizes, int n_in,
                              void* d_out, int out_size)
{
    const float* x    = (const float*)d_in[0];
    const float* W    = (const float*)d_in[1];
    const float* bias = (const float*)d_in[2];
    float* out        = (float*)d_out;

    prep_x_kernel<<<(M_ROWS * C_DIM + 255) / 256, 256>>>(x);
    prep_w_kernel<<<dim3(C3 / 32, C_DIM / 32), dim3(32, 8)>>>(W);

    cudaFuncSetAttribute(qkv_mma_kernel,
                         cudaFuncAttributeMaxDynamicSharedMemorySize, GEMM_SMEM);
    qkv_mma_kernel<<<dim3(C3 / 128, M_ROWS / 128), 256, GEMM_SMEM>>>(bias);

    cudaFuncSetAttribute(attn_mma_kernel,
                         cudaFuncAttributeMaxDynamicSharedMemorySize, ATTN_SMEM);
    attn_mma_kernel<<<dim3(8, NBH), 256, ATTN_SMEM>>>(out);
}